// round 6
// baseline (speedup 1.0000x reference)
#include <cuda_runtime.h>
#include <cuda_bf16.h>
#include <cstdint>

// ============================================================================
// Attention_84129819394524 — bf16-split mma.sync, 4-stage k16 pipeline
//   C = A @ B^T, fp32 x ≈ hi + lo (bf16); C = hi*hi + hi*lo + lo*hi.
//   (tcgen05 unavailable: harness ptxas targets sm_100 without 'a' features)
// ============================================================================

#define NUM_HEADS 12
#define HEAD_DIM  64
#define DIMC      768
#define BATCH     4
#define SEQ       1024
#define SCALE_F   0.125f

#define M_TOK   (BATCH * SEQ)          // 4096
#define QKV_N   (3 * DIMC)             // 2304
#define BH      (BATCH * NUM_HEADS)    // 48

#define OUT_ELEMS  ((size_t)M_TOK * DIMC)
#define ATTN_ELEMS ((size_t)BH * SEQ * SEQ)

// ---------------- device scratch (allocation-free) ----------------
__device__ __align__(16) __nv_bfloat16 g_xh [M_TOK * DIMC];
__device__ __align__(16) __nv_bfloat16 g_xl [M_TOK * DIMC];
__device__ __align__(16) __nv_bfloat16 g_wqh[QKV_N * DIMC];
__device__ __align__(16) __nv_bfloat16 g_wql[QKV_N * DIMC];
__device__ __align__(16) __nv_bfloat16 g_wph[DIMC * DIMC];
__device__ __align__(16) __nv_bfloat16 g_wpl[DIMC * DIMC];
__device__ __align__(16) __nv_bfloat16 g_qh [BH * SEQ * HEAD_DIM];
__device__ __align__(16) __nv_bfloat16 g_ql [BH * SEQ * HEAD_DIM];
__device__ __align__(16) __nv_bfloat16 g_kh [BH * SEQ * HEAD_DIM];
__device__ __align__(16) __nv_bfloat16 g_kl [BH * SEQ * HEAD_DIM];
__device__ __align__(16) __nv_bfloat16 g_vth[BH * HEAD_DIM * SEQ];   // V^T
__device__ __align__(16) __nv_bfloat16 g_vtl[BH * HEAD_DIM * SEQ];
__device__ __align__(16) __nv_bfloat16 g_ph [BH * SEQ * SEQ];
__device__ __align__(16) __nv_bfloat16 g_pl [BH * SEQ * SEQ];
__device__ __align__(16) __nv_bfloat16 g_oh [M_TOK * DIMC];
__device__ __align__(16) __nv_bfloat16 g_ol [M_TOK * DIMC];
__device__ __align__(256) float g_attn[ATTN_ELEMS];
__device__ __align__(256) float g_outs[OUT_ELEMS];

// ---------------- PTX helpers ----------------
__device__ __forceinline__ uint32_t smem_u32(const void* p) {
    return (uint32_t)__cvta_generic_to_shared(p);
}
__device__ __forceinline__ void cpasync16(uint32_t dst, const void* src) {
    asm volatile("cp.async.cg.shared.global [%0], [%1], 16;" :: "r"(dst), "l"(src));
}
__device__ __forceinline__ void ldsm_x4(uint32_t* r, uint32_t addr) {
    asm volatile("ldmatrix.sync.aligned.m8n8.x4.shared.b16 {%0,%1,%2,%3}, [%4];"
                 : "=r"(r[0]), "=r"(r[1]), "=r"(r[2]), "=r"(r[3]) : "r"(addr));
}
__device__ __forceinline__ void mma16816(float* c, const uint32_t* a, const uint32_t* b) {
    asm volatile("mma.sync.aligned.m16n8k16.row.col.f32.bf16.bf16.f32 "
                 "{%0,%1,%2,%3}, {%4,%5,%6,%7}, {%8,%9}, {%0,%1,%2,%3};"
                 : "+f"(c[0]), "+f"(c[1]), "+f"(c[2]), "+f"(c[3])
                 : "r"(a[0]), "r"(a[1]), "r"(a[2]), "r"(a[3]), "r"(b[0]), "r"(b[1]));
}
__device__ __forceinline__ void split2(float v, __nv_bfloat16& h, __nv_bfloat16& l) {
    h = __float2bfloat16_rn(v);
    l = __float2bfloat16_rn(v - __bfloat162float(h));
}

// ============================================================================
// Mainloop: block computes 128 x BN of C = A @ B^T, K mult of 16 (>=64).
// 256 threads, warps 4(m) x 2(n).  4-stage k16 cp.async pipeline, ONE
// __syncthreads per stage.  smem rows: 16 halfs padded to SPAD=24 (48B) —
// ldsm chunk index (3r)%8 distinct over 8 rows -> conflict-free.
// ============================================================================
#define SPAD 24

template<int BN>
__device__ __forceinline__ void gemm_tile(
    const __nv_bfloat16* __restrict__ Agh, const __nv_bfloat16* __restrict__ Agl, int lda,
    const __nv_bfloat16* __restrict__ Bgh, const __nv_bfloat16* __restrict__ Bgl, int ldb,
    int K, float (&acc)[2][BN / 16][4])
{
    extern __shared__ char smem_raw[];
    constexpr int NT  = BN / 16;
    constexpr int ASTB = 128 * SPAD * 2;        // bytes of one A subtile (hi or lo)
    constexpr int BSTB = BN  * SPAD * 2;
    constexpr int STAGEB = 2 * ASTB + 2 * BSTB;

    const int tid  = threadIdx.x;
    const int lane = tid & 31;
    const int warp = tid >> 5;
    const int wm = (warp >> 1) * 32;
    const int wn = (warp & 1) * (BN / 2);
    const uint32_t sb0 = smem_u32(smem_raw);

    const int lrow = tid >> 1;          // 0..127
    const int lch  = tid & 1;           // 16B chunk (8 halfs) within k16 row

    auto load_stage = [&](int buf, int k0) {
        uint32_t base = sb0 + (uint32_t)buf * STAGEB;
        uint32_t doff = (uint32_t)(lrow * SPAD + lch * 8) * 2;
        cpasync16(base + doff,        Agh + (size_t)lrow * lda + k0 + lch * 8);
        cpasync16(base + ASTB + doff, Agl + (size_t)lrow * lda + k0 + lch * 8);
        if (BN == 128) {
            cpasync16(base + 2 * ASTB + doff,        Bgh + (size_t)lrow * ldb + k0 + lch * 8);
            cpasync16(base + 2 * ASTB + BSTB + doff, Bgl + (size_t)lrow * ldb + k0 + lch * 8);
        } else {
            if (tid < 2 * BN) {
                cpasync16(base + 2 * ASTB + doff,        Bgh + (size_t)lrow * ldb + k0 + lch * 8);
                cpasync16(base + 2 * ASTB + BSTB + doff, Bgl + (size_t)lrow * ldb + k0 + lch * 8);
            }
        }
        asm volatile("cp.async.commit_group;");
    };

    const int niter = K >> 4;           // k16 stages, >= 4 for all our GEMMs
    load_stage(0, 0);
    load_stage(1, 16);
    load_stage(2, 32);

    const int a_row = wm + (lane & 15);
    const int a_ch  = lane >> 4;                    // k8 half
    const int g     = lane >> 3;
    const int b_row = wn + (g >> 1) * 8 + (lane & 7);
    const int b_ch  = g & 1;

    for (int it = 0; it < niter; it++) {
        asm volatile("cp.async.wait_group 2;");
        __syncthreads();
        const uint32_t sb = sb0 + (uint32_t)(it & 3) * STAGEB;

        uint32_t ah[2][4], al[2][4];
#pragma unroll
        for (int mt = 0; mt < 2; mt++) {
            uint32_t addr = sb + (uint32_t)(((a_row + mt * 16) * SPAD + a_ch * 8) * 2);
            ldsm_x4(ah[mt], addr);
            ldsm_x4(al[mt], addr + ASTB);
        }
        uint32_t bhf[NT][2], blf[NT][2];
#pragma unroll
        for (int u = 0; u < NT; u += 2) {
            uint32_t addr = sb + 2 * ASTB +
                (uint32_t)(((b_row + u * 8) * SPAD + b_ch * 8) * 2);
            uint32_t t[4];
            ldsm_x4(t, addr);
            bhf[u][0] = t[0]; bhf[u][1] = t[1];
            bhf[u + 1][0] = t[2]; bhf[u + 1][1] = t[3];
            ldsm_x4(t, addr + BSTB);
            blf[u][0] = t[0]; blf[u][1] = t[1];
            blf[u + 1][0] = t[2]; blf[u + 1][1] = t[3];
        }

        // prefetch stage it+3 while MMAs run (empty commit keeps group count uniform)
        if (it + 3 < niter) load_stage((it + 3) & 3, (it + 3) * 16);
        else asm volatile("cp.async.commit_group;");

#pragma unroll
        for (int mt = 0; mt < 2; mt++) {
#pragma unroll
            for (int u = 0; u < NT; u++) {
                mma16816(acc[mt][u], ah[mt], bhf[u]);
                mma16816(acc[mt][u], ah[mt], blf[u]);
                mma16816(acc[mt][u], al[mt], bhf[u]);
            }
        }
    }
}

// ============================================================================
// split: fp32 -> (hi, lo) bf16
// ============================================================================
__global__ __launch_bounds__(256)
void split_kernel(const float4* __restrict__ src, __nv_bfloat162* __restrict__ hi,
                  __nv_bfloat162* __restrict__ lo, int n4)
{
    int i = blockIdx.x * blockDim.x + threadIdx.x;
    if (i >= n4) return;
    float4 v = src[i];
    __nv_bfloat16 h0, h1, h2, h3, l0, l1, l2, l3;
    split2(v.x, h0, l0); split2(v.y, h1, l1);
    split2(v.z, h2, l2); split2(v.w, h3, l3);
    hi[2 * i]     = __nv_bfloat162(h0, h1);
    hi[2 * i + 1] = __nv_bfloat162(h2, h3);
    lo[2 * i]     = __nv_bfloat162(l0, l1);
    lo[2 * i + 1] = __nv_bfloat162(l2, l3);
}

// ============================================================================
// K1: QKV GEMM [4096 x 2304].  Epilogue: q (scaled) / k -> [B,H,S,D] hi/lo;
// v -> transposed [B,H,D,S] hi/lo (vt fused, no separate transpose kernel).
// ============================================================================
__global__ __launch_bounds__(256, 2)
void qkv_mma()
{
    float acc[2][8][4];
#pragma unroll
    for (int a = 0; a < 2; a++)
#pragma unroll
        for (int b = 0; b < 8; b++)
#pragma unroll
            for (int c = 0; c < 4; c++) acc[a][b][c] = 0.f;

    const int bx = blockIdx.x, by = blockIdx.y;
    gemm_tile<128>(g_xh + (size_t)(by * 128) * DIMC, g_xl + (size_t)(by * 128) * DIMC, DIMC,
                   g_wqh + (size_t)(bx * 128) * DIMC, g_wql + (size_t)(bx * 128) * DIMC, DIMC,
                   DIMC, acc);

    const int lane = threadIdx.x & 31, warp = threadIdx.x >> 5;
    const int wm = (warp >> 1) * 32, wn = (warp & 1) * 64;
    const int r = lane >> 2, cc = (lane & 3) * 2;

    const int which = bx / 6;           // 0:q 1:k 2:v
    const int cbase = bx * 128 - which * DIMC;

    if (which < 2) {
        __nv_bfloat16* dh = which ? g_kh : g_qh;
        __nv_bfloat16* dl = which ? g_kl : g_ql;
        const float scl = which ? 1.f : SCALE_F;
#pragma unroll
        for (int mt = 0; mt < 2; mt++) {
#pragma unroll
            for (int nt = 0; nt < 8; nt++) {
                int c = cbase + wn + nt * 8 + cc;
                int h = c >> 6, d = c & 63;
#pragma unroll
                for (int half = 0; half < 2; half++) {
                    int m = by * 128 + wm + mt * 16 + r + half * 8;
                    int b = m >> 10, qi = m & 1023;
                    size_t idx = (((size_t)(b * NUM_HEADS + h) * SEQ) + qi) * HEAD_DIM + d;
                    float v0 = acc[mt][nt][half * 2]     * scl;
                    float v1 = acc[mt][nt][half * 2 + 1] * scl;
                    __nv_bfloat16 h0, h1, l0, l1;
                    split2(v0, h0, l0); split2(v1, h1, l1);
                    *(__nv_bfloat162*)&dh[idx] = __nv_bfloat162(h0, h1);
                    *(__nv_bfloat162*)&dl[idx] = __nv_bfloat162(l0, l1);
                }
            }
        }
    } else {
        // V: write transposed  vt[bh][d][qi]
#pragma unroll
        for (int mt = 0; mt < 2; mt++) {
#pragma unroll
            for (int nt = 0; nt < 8; nt++) {
                int c = cbase + wn + nt * 8 + cc;
                int h = c >> 6, d = c & 63;
#pragma unroll
                for (int half = 0; half < 2; half++) {
                    int m = by * 128 + wm + mt * 16 + r + half * 8;
                    int b = m >> 10, qi = m & 1023;
                    size_t tb = ((size_t)(b * NUM_HEADS + h) * HEAD_DIM + d) * SEQ + qi;
                    float v0 = acc[mt][nt][half * 2];
                    float v1 = acc[mt][nt][half * 2 + 1];
                    __nv_bfloat16 h0, h1, l0, l1;
                    split2(v0, h0, l0); split2(v1, h1, l1);
                    g_vth[tb]       = h0;  g_vtl[tb]       = l0;
                    g_vth[tb + SEQ] = h1;  g_vtl[tb + SEQ] = l1;
                }
            }
        }
    }
}

// ============================================================================
// K2: S = q @ k^T per (b,h).  128x128, K=64.
// ============================================================================
__global__ __launch_bounds__(256, 2)
void s_mma(float* attn_out)
{
    float* attn = attn_out ? attn_out : g_attn;
    float acc[2][8][4];
#pragma unroll
    for (int a = 0; a < 2; a++)
#pragma unroll
        for (int b = 0; b < 8; b++)
#pragma unroll
            for (int c = 0; c < 4; c++) acc[a][b][c] = 0.f;

    const int bh = blockIdx.z, bx = blockIdx.x, by = blockIdx.y;
    const size_t hb = (size_t)bh * SEQ * HEAD_DIM;
    gemm_tile<128>(g_qh + hb + (size_t)(by * 128) * HEAD_DIM,
                   g_ql + hb + (size_t)(by * 128) * HEAD_DIM, HEAD_DIM,
                   g_kh + hb + (size_t)(bx * 128) * HEAD_DIM,
                   g_kl + hb + (size_t)(bx * 128) * HEAD_DIM, HEAD_DIM,
                   HEAD_DIM, acc);

    const int lane = threadIdx.x & 31, warp = threadIdx.x >> 5;
    const int wm = (warp >> 1) * 32, wn = (warp & 1) * 64;
    const int r = lane >> 2, cc = (lane & 3) * 2;
    float* C = attn + (size_t)bh * SEQ * SEQ;

#pragma unroll
    for (int mt = 0; mt < 2; mt++) {
#pragma unroll
        for (int nt = 0; nt < 8; nt++) {
            int n = bx * 128 + wn + nt * 8 + cc;
#pragma unroll
            for (int half = 0; half < 2; half++) {
                int m = by * 128 + wm + mt * 16 + r + half * 8;
                *(float2*)&C[(size_t)m * SEQ + n] =
                    make_float2(acc[mt][nt][half * 2], acc[mt][nt][half * 2 + 1]);
            }
        }
    }
}

// ============================================================================
// K3: row softmax in place + emit P hi/lo bf16
// ============================================================================
__global__ __launch_bounds__(256)
void softmax_kernel(float* attn_out)
{
    float* attn = attn_out ? attn_out : g_attn;
    float* p = attn + (size_t)blockIdx.x * SEQ;
    const size_t pbase = (size_t)blockIdx.x * SEQ;
    const int tid = threadIdx.x;
    __shared__ float red_max[8];
    __shared__ float red_sum[8];

    float4 v = reinterpret_cast<float4*>(p)[tid];
    float m = fmaxf(fmaxf(v.x, v.y), fmaxf(v.z, v.w));
#pragma unroll
    for (int o = 16; o > 0; o >>= 1) m = fmaxf(m, __shfl_xor_sync(0xFFFFFFFFu, m, o));
    if ((tid & 31) == 0) red_max[tid >> 5] = m;
    __syncthreads();
    if (tid == 0) {
        float t = red_max[0];
#pragma unroll
        for (int i = 1; i < 8; i++) t = fmaxf(t, red_max[i]);
        red_max[0] = t;
    }
    __syncthreads();
    const float rmax = red_max[0];

    v.x = expf(v.x - rmax); v.y = expf(v.y - rmax);
    v.z = expf(v.z - rmax); v.w = expf(v.w - rmax);
    float s = v.x + v.y + v.z + v.w;
#pragma unroll
    for (int o = 16; o > 0; o >>= 1) s += __shfl_xor_sync(0xFFFFFFFFu, s, o);
    if ((tid & 31) == 0) red_sum[tid >> 5] = s;
    __syncthreads();
    if (tid == 0) {
        float t = 0.f;
#pragma unroll
        for (int i = 0; i < 8; i++) t += red_sum[i];
        red_sum[0] = t;
    }
    __syncthreads();
    const float inv = 1.0f / red_sum[0];
    v.x *= inv; v.y *= inv; v.z *= inv; v.w *= inv;
    reinterpret_cast<float4*>(p)[tid] = v;

    __nv_bfloat16 h0, h1, h2, h3, l0, l1, l2, l3;
    split2(v.x, h0, l0); split2(v.y, h1, l1);
    split2(v.z, h2, l2); split2(v.w, h3, l3);
    size_t idx = pbase + tid * 4;
    *(__nv_bfloat162*)&g_ph[idx]     = __nv_bfloat162(h0, h1);
    *(__nv_bfloat162*)&g_ph[idx + 2] = __nv_bfloat162(h2, h3);
    *(__nv_bfloat162*)&g_pl[idx]     = __nv_bfloat162(l0, l1);
    *(__nv_bfloat162*)&g_pl[idx + 2] = __nv_bfloat162(l2, l3);
}

// ============================================================================
// K4: O = P @ vt^T per (b,h).  128x64, K=1024.  -> O hi/lo in [B,S,C]
// ============================================================================
__global__ __launch_bounds__(256, 2)
void o_mma()
{
    float acc[2][4][4];
#pragma unroll
    for (int a = 0; a < 2; a++)
#pragma unroll
        for (int b = 0; b < 4; b++)
#pragma unroll
            for (int c = 0; c < 4; c++) acc[a][b][c] = 0.f;

    const int bh = blockIdx.y, bx = blockIdx.x;
    const int b = bh / NUM_HEADS, h = bh - b * NUM_HEADS;
    gemm_tile<64>(g_ph + (size_t)bh * SEQ * SEQ + (size_t)(bx * 128) * SEQ,
                  g_pl + (size_t)bh * SEQ * SEQ + (size_t)(bx * 128) * SEQ, SEQ,
                  g_vth + (size_t)bh * HEAD_DIM * SEQ,
                  g_vtl + (size_t)bh * HEAD_DIM * SEQ, SEQ,
                  SEQ, acc);

    const int lane = threadIdx.x & 31, warp = threadIdx.x >> 5;
    const int wm = (warp >> 1) * 32, wn = (warp & 1) * 32;
    const int r = lane >> 2, cc = (lane & 3) * 2;

#pragma unroll
    for (int mt = 0; mt < 2; mt++) {
#pragma unroll
        for (int nt = 0; nt < 4; nt++) {
            int d = wn + nt * 8 + cc;
#pragma unroll
            for (int half = 0; half < 2; half++) {
                int mseq = bx * 128 + wm + mt * 16 + r + half * 8;
                size_t idx = ((size_t)b * SEQ + mseq) * DIMC + h * HEAD_DIM + d;
                float v0 = acc[mt][nt][half * 2];
                float v1 = acc[mt][nt][half * 2 + 1];
                __nv_bfloat16 h0, h1, l0, l1;
                split2(v0, h0, l0); split2(v1, h1, l1);
                *(__nv_bfloat162*)&g_oh[idx] = __nv_bfloat162(h0, h1);
                *(__nv_bfloat162*)&g_ol[idx] = __nv_bfloat162(l0, l1);
            }
        }
    }
}

// ============================================================================
// K5: out = O @ w_proj^T + bias.  [4096 x 768], K=768, fp32 out.
// ============================================================================
__global__ __launch_bounds__(256, 2)
void proj_mma(const float* __restrict__ bias, float* out_ptr)
{
    float* outp = out_ptr ? out_ptr : g_outs;
    float acc[2][8][4];
#pragma unroll
    for (int a = 0; a < 2; a++)
#pragma unroll
        for (int b = 0; b < 8; b++)
#pragma unroll
            for (int c = 0; c < 4; c++) acc[a][b][c] = 0.f;

    const int bx = blockIdx.x, by = blockIdx.y;
    gemm_tile<128>(g_oh + (size_t)(by * 128) * DIMC, g_ol + (size_t)(by * 128) * DIMC, DIMC,
                   g_wph + (size_t)(bx * 128) * DIMC, g_wpl + (size_t)(bx * 128) * DIMC, DIMC,
                   DIMC, acc);

    const int lane = threadIdx.x & 31, warp = threadIdx.x >> 5;
    const int wm = (warp >> 1) * 32, wn = (warp & 1) * 64;
    const int r = lane >> 2, cc = (lane & 3) * 2;

#pragma unroll
    for (int mt = 0; mt < 2; mt++) {
#pragma unroll
        for (int nt = 0; nt < 8; nt++) {
            int n = bx * 128 + wn + nt * 8 + cc;
            float b0 = bias[n], b1 = bias[n + 1];
#pragma unroll
            for (int half = 0; half < 2; half++) {
                int m = by * 128 + wm + mt * 16 + r + half * 8;
                *(float2*)&outp[(size_t)m * DIMC + n] =
                    make_float2(acc[mt][nt][half * 2] + b0, acc[mt][nt][half * 2 + 1] + b1);
            }
        }
    }
}

// ============================================================================
// launch
// ============================================================================
extern "C" void kernel_launch(void* const* d_in, const int* in_sizes, int n_in,
                              void* d_out, int out_size)
{
    const float* x      = (const float*)d_in[0];
    const float* w_qkv  = (const float*)d_in[1];
    const float* w_proj = (const float*)d_in[2];
    const float* b_proj = (const float*)d_in[3];
    (void)in_sizes; (void)n_in;

    float* dof = (float*)d_out;
    float* out_ptr  = nullptr;
    float* attn_ptr = nullptr;
    size_t osz = (size_t)out_size;
    if (osz >= OUT_ELEMS + ATTN_ELEMS) { out_ptr = dof; attn_ptr = dof + OUT_ELEMS; }
    else if (osz == ATTN_ELEMS)        { attn_ptr = dof; }
    else                               { out_ptr = dof; }

    // dynamic smem: 4 stages
    const int SM_BIG = 4 * (2 * 128 * SPAD * 2 + 2 * 128 * SPAD * 2);  // 98304
    const int SM_O   = 4 * (2 * 128 * SPAD * 2 + 2 * 64  * SPAD * 2);  // 73728
    cudaFuncSetAttribute(qkv_mma,  cudaFuncAttributeMaxDynamicSharedMemorySize, SM_BIG);
    cudaFuncSetAttribute(s_mma,    cudaFuncAttributeMaxDynamicSharedMemorySize, SM_BIG);
    cudaFuncSetAttribute(proj_mma, cudaFuncAttributeMaxDynamicSharedMemorySize, SM_BIG);
    cudaFuncSetAttribute(o_mma,    cudaFuncAttributeMaxDynamicSharedMemorySize, SM_O);

    void *p_xh, *p_xl, *p_wqh, *p_wql, *p_wph, *p_wpl;
    cudaGetSymbolAddress(&p_xh, g_xh);   cudaGetSymbolAddress(&p_xl, g_xl);
    cudaGetSymbolAddress(&p_wqh, g_wqh); cudaGetSymbolAddress(&p_wql, g_wql);
    cudaGetSymbolAddress(&p_wph, g_wph); cudaGetSymbolAddress(&p_wpl, g_wpl);

    dim3 blk(256);

    { int n4 = M_TOK * DIMC / 4;
      split_kernel<<<(n4 + 255) / 256, blk>>>((const float4*)x,
          (__nv_bfloat162*)p_xh, (__nv_bfloat162*)p_xl, n4); }
    { int n4 = QKV_N * DIMC / 4;
      split_kernel<<<(n4 + 255) / 256, blk>>>((const float4*)w_qkv,
          (__nv_bfloat162*)p_wqh, (__nv_bfloat162*)p_wql, n4); }
    { int n4 = DIMC * DIMC / 4;
      split_kernel<<<(n4 + 255) / 256, blk>>>((const float4*)w_proj,
          (__nv_bfloat162*)p_wph, (__nv_bfloat162*)p_wpl, n4); }

    qkv_mma<<<dim3(QKV_N / 128, M_TOK / 128), blk, SM_BIG>>>();

    s_mma<<<dim3(SEQ / 128, SEQ / 128, BH), blk, SM_BIG>>>(attn_ptr);

    softmax_kernel<<<dim3(BH * SEQ), blk>>>(attn_ptr);

    o_mma<<<dim3(SEQ / 128, BH), blk, SM_O>>>();

    proj_mma<<<dim3(DIMC / 128, M_TOK / 128), blk, SM_BIG>>>(b_proj, out_ptr);
}